// round 16
// baseline (speedup 1.0000x reference)
#include <cuda_runtime.h>
#include <cuda_fp16.h>
#include <cstdint>

#define BB 32
#define NN 128
#define IN_F 64
#define HID 128
#define OUTF 64
#define EE (NN*(NN-1))
#define DEG (NN-1)
#define NODE_OUT (BB*NN*OUTF)

// fp16-packed layout: u32 words, stride 68
#define ELDA 68
// edge kernel (M-tile 64): sA 64 rows, sB 128 rows
#define E2B_OFF (64*ELDA)
#define E2F_OFF (192*ELDA)
#define E2SMEM_BYTES ((192*ELDA + 768)*4)
#define EG2 456

// node-kernel layout: sA 64 rows, sB 128 rows
#define NA_ROWS 64
#define NB_OFF (NA_ROWS*ELDA)
#define NF_OFF (NB_OFF + 128*ELDA)
#define NSMEM_BYTES ((NF_OFF + 768)*4)

// ---- scratch (device globals, allocation-free) ----
__device__ float g_P[BB*NN*HID];
__device__ float g_R[BB*NN*HID];
__device__ float g_pSu[EG2*HID];
__device__ float g_pQu[EG2*HID];
__device__ float g_inc[BB*NN*HID];
__device__ float g_eka[HID];
__device__ float g_ekb[HID];
__device__ float g_hn2[BB*NN*HID];
__device__ float g_nS[2*BB*HID];
__device__ float g_nQ[2*BB*HID];
__device__ float g_nka[HID];
__device__ float g_nkb[HID];
__device__ float g_o[BB*NN*OUTF];
__device__ float g_mS[2*BB*OUTF];
__device__ float g_mQ[2*BB*OUTF];
__device__ float g_mka[OUTF];
__device__ float g_mkb[OUTF];
__device__ uint32_t g_h2[BB*EE*HID/2];

__device__ __forceinline__ float siluf(float x){
  float h = 0.5f * x;
  float t;
  asm("tanh.approx.f32 %0, %1;" : "=f"(t) : "f"(h));
  return fmaf(h, t, h);
}
__device__ __forceinline__ uint32_t packh2(float a, float b){
  __half2 h = __floats2half2_rn(a, b);
  return *(uint32_t*)&h;
}
__device__ __forceinline__ uint32_t smem_addr_u32(const void* p){
  return (uint32_t)__cvta_generic_to_shared(p);
}
__device__ __forceinline__ void zero_acc2(float (&acc)[2][4][4]){
  #pragma unroll
  for (int i=0;i<2;i++)
    #pragma unroll
    for (int j=0;j<4;j++)
      #pragma unroll
      for (int k=0;k<4;k++) acc[i][j][k]=0.f;
}

// fp16 ldmatrix+mma: 64x128 tile, 8 warps (2m x 4n, 32x32)
__device__ __forceinline__ void mma_fp16_64(float (&acc)[2][4][4],
                                            const uint32_t aA[2], const uint32_t bA[4],
                                            int Kw)
{
  for (int kw0 = 0; kw0 < Kw; kw0 += 8){
    uint32_t a[2][4];
    #pragma unroll
    for (int mi = 0; mi < 2; mi++)
      asm volatile(
        "ldmatrix.sync.aligned.m8n8.x4.shared.b16 {%0,%1,%2,%3}, [%4];"
        : "=r"(a[mi][0]), "=r"(a[mi][1]), "=r"(a[mi][2]), "=r"(a[mi][3])
        : "r"(aA[mi] + kw0*4));
    uint32_t bf[4][2];
    #pragma unroll
    for (int ni = 0; ni < 4; ni++)
      asm volatile(
        "ldmatrix.sync.aligned.m8n8.x2.shared.b16 {%0,%1}, [%2];"
        : "=r"(bf[ni][0]), "=r"(bf[ni][1])
        : "r"(bA[ni] + kw0*4));
    #pragma unroll
    for (int mi = 0; mi < 2; mi++)
      #pragma unroll
      for (int ni = 0; ni < 4; ni++)
        asm volatile(
          "mma.sync.aligned.m16n8k16.row.col.f32.f16.f16.f32 "
          "{%0,%1,%2,%3},{%4,%5,%6,%7},{%8,%9},{%0,%1,%2,%3};\n"
          : "+f"(acc[mi][ni][0]), "+f"(acc[mi][ni][1]),
            "+f"(acc[mi][ni][2]), "+f"(acc[mi][ni][3])
          : "r"(a[mi][0]), "r"(a[mi][1]), "r"(a[mi][2]), "r"(a[mi][3]),
            "r"(bf[ni][0]), "r"(bf[ni][1]));
  }
}

// ---- P/R precompute ----
__global__ void k_pr(const float* __restrict__ x, const float* __restrict__ eW1,
                     const float* __restrict__ eb1)
{
  extern __shared__ float sw[];
  float* sx = sw + 128*128;
  int tid = threadIdx.x;
  int n0 = blockIdx.x * 8;
  for (int idx = tid; idx < 128*128; idx += 256) sw[idx] = eW1[idx];
  for (int idx = tid; idx < 8*64; idx += 256)
    sx[idx] = x[(size_t)n0*IN_F + idx];
  __syncthreads();
  int c = tid & 127;
  for (int it = 0; it < 4; it++){
    int nl = it*2 + (tid >> 7);
    const float* xr = sx + nl*64;
    float p = 0.f, r = 0.f;
    #pragma unroll 8
    for (int k = 0; k < 64; k++){
      float xv = xr[k];
      p += xv * sw[k*128 + c];
      r += xv * sw[(64+k)*128 + c];
    }
    size_t o = (size_t)(n0 + nl)*HID + c;
    g_P[o] = p;
    g_R[o] = r + eb1[c];
  }
}

// ---- persistent edge kernel: M-tile 64, 3 CTAs/SM ----
__global__ void __launch_bounds__(256,3)
k_edge(const float* __restrict__ eW2, const float* __restrict__ eb2)
{
  extern __shared__ uint32_t sm[];
  uint32_t* sA = sm;
  uint32_t* sB = sm + E2B_OFF;
  float* sF  = (float*)(sm + E2F_OFF);
  float* sR  = sF;       float* sb2 = sF+128;
  float* sPSu= sF+256;   float* sPQu= sF+512;

  int tid = threadIdx.x, lane = tid & 31, wid = tid >> 5;
  int wm = wid >> 2, wn = wid & 3;
  int g = lane >> 2, t4 = lane & 3;

  for (int idx = tid; idx < 64*128; idx += 256){
    int kw = idx >> 7, n = idx & 127;
    sB[n*ELDA + kw] = packh2(eW2[(2*kw)*HID + n], eW2[(2*kw+1)*HID + n]);
  }
  if (tid < 128) sb2[tid] = eb2[tid];
  __syncthreads();

  uint32_t aAddr[2], bAddr[4];
  {
    int arow = wm*32 + (lane & 15);
    int akw  = (lane >> 4) * 4;
    #pragma unroll
    for (int mi = 0; mi < 2; mi++)
      aAddr[mi] = smem_addr_u32(sA + (arow + mi*16)*ELDA + akw);
    int brow = wn*32 + (lane & 7);
    int bkw  = ((lane >> 3) & 1) * 4;
    #pragma unroll
    for (int ni = 0; ni < 4; ni++)
      bAddr[ni] = smem_addr_u32(sB + (brow + ni*8)*ELDA + bkw);
  }

  float aSu[8], aSq[8];
  #pragma unroll
  for (int q=0;q<8;q++){ aSu[q]=0.f; aSq[q]=0.f; }

  for (int half = blockIdx.x; half < 2*BB*NN; half += EG2){
    int grp = half >> 1; int m0 = (half & 1)*64;
    int b = grp >> 7, i = grp & 127;
    if (tid < 128) sR[tid] = g_R[(size_t)grp*HID + tid];
    __syncthreads();

    { // A rows: 64 rows x 4 quarters of 32 cols
      int r = tid >> 2, h = tid & 3;
      int re = m0 + r;
      uint2* Ar2 = (uint2*)(sA + r*ELDA + h*16);
      if (re < DEG){
        int j = (re < i) ? re : re + 1;
        const float* Pr = g_P + ((size_t)(b*NN + j))*HID + h*32;
        const float* Rr = sR + h*32;
        #pragma unroll
        for (int c = 0; c < 32; c += 4){
          float4 p = *(const float4*)(Pr + c);
          float x0 = siluf(p.x + Rr[c]);
          float x1 = siluf(p.y + Rr[c+1]);
          float x2 = siluf(p.z + Rr[c+2]);
          float x3 = siluf(p.w + Rr[c+3]);
          Ar2[c/4] = make_uint2(packh2(x0, x1), packh2(x2, x3));
        }
      } else {
        #pragma unroll
        for (int w = 0; w < 8; w++) Ar2[w] = make_uint2(0u, 0u);
      }
    }
    __syncthreads();

    float acc[2][4][4]; zero_acc2(acc);
    mma_fp16_64(acc, aAddr, bAddr, 64);

    size_t obase2 = ((size_t)grp*DEG*HID) >> 1;
    #pragma unroll
    for (int mi = 0; mi < 2; mi++)
      #pragma unroll
      for (int rr = 0; rr < 2; rr++){
        int re = m0 + wm*32 + mi*16 + g + rr*8;
        if (re < DEG){
          #pragma unroll
          for (int ni = 0; ni < 4; ni++){
            int col = wn*32 + ni*8 + 2*t4;
            float v0 = siluf(acc[mi][ni][rr*2+0] + sb2[col]);
            float v1 = siluf(acc[mi][ni][rr*2+1] + sb2[col+1]);
            g_h2[obase2 + (((size_t)re*HID + col) >> 1)] = packh2(v0, v1);
            aSu[ni*2+0]+=v0; aSq[ni*2+0]+=v0*v0;
            aSu[ni*2+1]+=v1; aSq[ni*2+1]+=v1*v1;
          }
        }
      }
    __syncthreads();
  }

  #pragma unroll
  for (int q = 0; q < 8; q++){
    #pragma unroll
    for (int mk = 4; mk <= 16; mk <<= 1){
      aSu[q] += __shfl_xor_sync(0xffffffffu, aSu[q], mk);
      aSq[q] += __shfl_xor_sync(0xffffffffu, aSq[q], mk);
    }
  }
  if (g == 0){
    #pragma unroll
    for (int ni = 0; ni < 4; ni++){
      int col = wn*32 + ni*8 + 2*t4;
      sPSu[wm*128+col]   = aSu[ni*2];   sPSu[wm*128+col+1] = aSu[ni*2+1];
      sPQu[wm*128+col]   = aSq[ni*2];   sPQu[wm*128+col+1] = aSq[ni*2+1];
    }
  }
  __syncthreads();
  if (tid < 128){
    g_pSu[(size_t)blockIdx.x*HID + tid] = sPSu[tid] + sPSu[128+tid];
    g_pQu[(size_t)blockIdx.x*HID + tid] = sPQu[tid] + sPQu[128+tid];
  }
}

// ---- edge BN coefficients ----
__global__ void k_ecol(const float* __restrict__ eg, const float* __restrict__ ebt){
  __shared__ float rS[256], rQ[256];
  int c = blockIdx.x, t = threadIdx.x;
  float s=0.f, q=0.f;
  for (int r=t; r<EG2; r+=256){ s += g_pSu[r*HID+c]; q += g_pQu[r*HID+c]; }
  rS[t]=s; rQ[t]=q; __syncthreads();
  for (int o=128;o>0;o>>=1){ if(t<o){rS[t]+=rS[t+o];rQ[t]+=rQ[t+o];} __syncthreads(); }
  if (t==0){
    float inv = 1.f/((float)BB*(float)EE);
    float m = rS[0]*inv, v = rQ[0]*inv - m*m;
    float ka = eg[c]/sqrtf(v+1e-5f);
    g_eka[c]=ka; g_ekb[c]=ebt[c]-m*ka;
  }
}

// ---- BN affine * em^2 per group (grid=4096) ----
__global__ void k_affine(const float* __restrict__ em, float* __restrict__ mij){
  __shared__ float ka[HID], kb[HID], sEm[HID];
  __shared__ float sP[8*HID];
  int grp = blockIdx.x; int b = grp >> 7; int i = grp & 127;
  int t = threadIdx.x;
  if (t < 128){ ka[t]=g_eka[t]; kb[t]=g_ekb[t]; }
  else {
    int r = t - 128;
    float e = (r < DEG) ? em[(size_t)b*EE + (size_t)i*DEG + r] : 0.f;
    sEm[r] = e*e;
  }
  __syncthreads();
  int wp = t & 31;
  int rh = t >> 5;
  int c4 = wp*4;
  float k0=ka[c4],  k1=ka[c4+1], k2=ka[c4+2], k3=ka[c4+3];
  float d0=kb[c4],  d1=kb[c4+1], d2=kb[c4+2], d3=kb[c4+3];
  float s0=0.f, s1=0.f, s2=0.f, s3=0.f;
  size_t gbase = ((size_t)grp*DEG*HID) >> 1;
  for (int r = rh; r < DEG; r += 8){
    uint2 p = *(const uint2*)(g_h2 + gbase + (size_t)r*64 + wp*2);
    float2 h0 = __half22float2(*(__half2*)&p.x);
    float2 h1 = __half22float2(*(__half2*)&p.y);
    float wgt = sEm[r];
    float v0 = (k0*h0.x + d0)*wgt;
    float v1 = (k1*h0.y + d1)*wgt;
    float v2 = (k2*h1.x + d2)*wgt;
    float v3 = (k3*h1.y + d3)*wgt;
    *(float4*)(mij + ((size_t)grp*DEG + r)*HID + c4) = make_float4(v0,v1,v2,v3);
    s0+=v0; s1+=v1; s2+=v2; s3+=v3;
  }
  float* row = sP + rh*HID + c4;
  row[0]=s0; row[1]=s1; row[2]=s2; row[3]=s3;
  __syncthreads();
  if (t < 128){
    float s = 0.f;
    #pragma unroll
    for (int q = 0; q < 8; q++) s += sP[q*HID + t];
    g_inc[(size_t)grp*HID + t] = s * (1.f/(float)NN);
  }
}

// ---- node MLP 1: grid 64, M-tile 64 ----
__global__ void __launch_bounds__(256,2)
k_node1(const float* __restrict__ nW1, const float* __restrict__ nb1,
        const float* __restrict__ nW2, const float* __restrict__ nb2)
{
  extern __shared__ uint32_t sm[];
  uint32_t* sA = sm; uint32_t* sB = sm + NB_OFF;
  float* sF = (float*)(sm + NF_OFF);
  float* sb1 = sF;     float* sb2v = sF+128;
  float* sSu = sF+256; float* sSq = sF+384;
  int bid = blockIdx.x; int b = bid >> 1; int m0 = (bid & 1)*64;
  int tid = threadIdx.x; int lane = tid & 31; int wid = tid >> 5;
  int wm = wid >> 2, wn = wid & 3, g = lane >> 2, t4 = lane & 3;

  uint32_t aAddr[2], bAddr[4];
  {
    int arow = wm*32 + (lane & 15);
    int akw  = (lane >> 4) * 4;
    #pragma unroll
    for (int mi = 0; mi < 2; mi++)
      aAddr[mi] = smem_addr_u32(sA + (arow + mi*16)*ELDA + akw);
    int brow = wn*32 + (lane & 7);
    int bkw  = ((lane >> 3) & 1) * 4;
    #pragma unroll
    for (int ni = 0; ni < 4; ni++)
      bAddr[ni] = smem_addr_u32(sB + (brow + ni*8)*ELDA + bkw);
  }

  if (tid < 128){
    sb1[tid]=nb1[tid];   sb2v[tid]=nb2[tid];
    sSu[tid]=0.f; sSq[tid]=0.f;
  }
  {
    int r = tid >> 2, h = tid & 3;
    const float* ir = g_inc + ((size_t)(b*NN + m0 + r))*HID + h*32;
    uint2* Ar2 = (uint2*)(sA + r*ELDA + h*16);
    #pragma unroll
    for (int c = 0; c < 32; c += 4){
      float4 v = *(const float4*)(ir + c);
      Ar2[c/4] = make_uint2(packh2(v.x, v.y), packh2(v.z, v.w));
    }
  }
  for (int idx = tid; idx < 64*128; idx += 256){
    int kw = idx >> 7, n = idx & 127;
    sB[n*ELDA + kw] = packh2(nW1[(2*kw)*HID + n], nW1[(2*kw+1)*HID + n]);
  }
  __syncthreads();
  float acc[2][4][4]; zero_acc2(acc);
  mma_fp16_64(acc, aAddr, bAddr, 64);
  __syncthreads();
  #pragma unroll
  for (int mi=0;mi<2;mi++)
    #pragma unroll
    for (int rr=0;rr<2;rr++){
      int r = wm*32 + mi*16 + g + rr*8;
      #pragma unroll
      for (int ni=0;ni<4;ni++){
        int col = wn*32 + ni*8 + 2*t4;
        float v0 = siluf(acc[mi][ni][rr*2+0] + sb1[col]);
        float v1 = siluf(acc[mi][ni][rr*2+1] + sb1[col+1]);
        sA[r*ELDA + (col>>1)] = packh2(v0, v1);
      }
    }
  for (int idx = tid; idx < 64*128; idx += 256){
    int kw = idx >> 7, n = idx & 127;
    sB[n*ELDA + kw] = packh2(nW2[(2*kw)*HID + n], nW2[(2*kw+1)*HID + n]);
  }
  __syncthreads();
  zero_acc2(acc);
  mma_fp16_64(acc, aAddr, bAddr, 64);
  float aSu[8], aSq[8];
  #pragma unroll
  for (int q=0;q<8;q++){ aSu[q]=0.f; aSq[q]=0.f; }
  #pragma unroll
  for (int mi=0;mi<2;mi++)
    #pragma unroll
    for (int rr=0;rr<2;rr++){
      int r = wm*32 + mi*16 + g + rr*8;
      #pragma unroll
      for (int ni=0;ni<4;ni++){
        int col = wn*32 + ni*8 + 2*t4;
        float v0 = siluf(acc[mi][ni][rr*2+0] + sb2v[col]);
        float v1 = siluf(acc[mi][ni][rr*2+1] + sb2v[col+1]);
        *(float2*)(g_hn2 + ((size_t)(b*NN + m0 + r))*HID + col) = make_float2(v0,v1);
        aSu[ni*2+0]+=v0; aSq[ni*2+0]+=v0*v0;
        aSu[ni*2+1]+=v1; aSq[ni*2+1]+=v1*v1;
      }
    }
  #pragma unroll
  for (int q = 0; q < 8; q++){
    #pragma unroll
    for (int mk = 4; mk <= 16; mk <<= 1){
      aSu[q] += __shfl_xor_sync(0xffffffffu, aSu[q], mk);
      aSq[q] += __shfl_xor_sync(0xffffffffu, aSq[q], mk);
    }
  }
  if (g == 0){
    #pragma unroll
    for (int ni=0;ni<4;ni++){
      int col = wn*32 + ni*8 + 2*t4;
      atomicAdd(&sSu[col], aSu[ni*2]);   atomicAdd(&sSu[col+1], aSu[ni*2+1]);
      atomicAdd(&sSq[col], aSq[ni*2]);   atomicAdd(&sSq[col+1], aSq[ni*2+1]);
    }
  }
  __syncthreads();
  if (tid < 128){ g_nS[bid*HID+tid]=sSu[tid]; g_nQ[bid*HID+tid]=sSq[tid]; }
}

__global__ void k_nred(const float* __restrict__ ng, const float* __restrict__ nbt){
  int c = threadIdx.x;
  float s=0.f, q=0.f;
  for (int b=0;b<2*BB;b++){ s+=g_nS[b*HID+c]; q+=g_nQ[b*HID+c]; }
  float inv = 1.f/((float)BB*NN);
  float m = s*inv, v = q*inv - m*m;
  float ka = ng[c]/sqrtf(v+1e-5f);
  g_nka[c]=ka; g_nkb[c]=nbt[c]-m*ka;
}

// ---- node MLP 2: grid 64, M-tile 64 ----
__global__ void __launch_bounds__(256,2)
k_node2(const float* __restrict__ x, const float* __restrict__ nmask,
        const float* __restrict__ mW1, const float* __restrict__ mb1,
        const float* __restrict__ mW2, const float* __restrict__ mb2)
{
  extern __shared__ uint32_t sm[];
  uint32_t* sA = sm; uint32_t* sB = sm + NB_OFF;
  float* sF = (float*)(sm + NF_OFF);
  float* ska = sF;     float* skb = sF+128;
  float* sb1 = sF+256; float* sb2v = sF+384;
  float* sSu = sF+512; float* sSq = sF+640;
  int bid = blockIdx.x; int b = bid >> 1; int m0 = (bid & 1)*64;
  int tid = threadIdx.x; int lane = tid & 31; int wid = tid >> 5;
  int wm = wid >> 2, wn = wid & 3, g = lane >> 2, t4 = lane & 3;

  uint32_t aAddr[2], bAddr[4];
  {
    int arow = wm*32 + (lane & 15);
    int akw  = (lane >> 4) * 4;
    #pragma unroll
    for (int mi = 0; mi < 2; mi++)
      aAddr[mi] = smem_addr_u32(sA + (arow + mi*16)*ELDA + akw);
    int brow = wn*32 + (lane & 7);
    int bkw  = ((lane >> 3) & 1) * 4;
    #pragma unroll
    for (int ni = 0; ni < 4; ni++)
      bAddr[ni] = smem_addr_u32(sB + (brow + ni*8)*ELDA + bkw);
  }

  if (tid < 128){
    ska[tid]=g_nka[tid]; skb[tid]=g_nkb[tid];
    sb1[tid]=mb1[tid];
    sSu[tid]=0.f; sSq[tid]=0.f;
  }
  if (tid < 64) sb2v[tid]=mb2[tid];
  {
    int r = tid >> 2, h = tid & 3;
    const float* xr = x + ((size_t)(b*NN + m0 + r))*IN_F + h*16;
    uint2* Ar2 = (uint2*)(sA + r*ELDA + h*8);
    #pragma unroll
    for (int c = 0; c < 16; c += 4){
      float4 v = *(const float4*)(xr + c);
      Ar2[c/4] = make_uint2(packh2(v.x, v.y), packh2(v.z, v.w));
    }
  }
  for (int idx = tid; idx < 32*128; idx += 256){
    int kw = idx >> 7, n = idx & 127;
    sB[n*ELDA + kw] = packh2(mW1[(2*kw)*HID + n], mW1[(2*kw+1)*HID + n]);
  }
  __syncthreads();
  float acc[2][4][4]; zero_acc2(acc);
  mma_fp16_64(acc, aAddr, bAddr, 32);
  __syncthreads();
  {
    int r = tid >> 2, h = tid & 3;
    int gr = b*NN + m0 + r;
    float msk = nmask[gr];
    const float* hr = g_hn2 + (size_t)gr*HID + h*32;
    const float* kap = ska + h*32; const float* kbp = skb + h*32;
    uint2* Ar2 = (uint2*)(sA + r*ELDA + h*16);
    #pragma unroll
    for (int c = 0; c < 32; c += 4){
      float v0 = (kap[c]*hr[c] + kbp[c]) * msk;
      float v1 = (kap[c+1]*hr[c+1] + kbp[c+1]) * msk;
      float v2 = (kap[c+2]*hr[c+2] + kbp[c+2]) * msk;
      float v3 = (kap[c+3]*hr[c+3] + kbp[c+3]) * msk;
      Ar2[c/4] = make_uint2(packh2(v0, v1), packh2(v2, v3));
    }
  }
  for (int idx = tid; idx < 64*128; idx += 256){
    int kw = idx >> 7, n = idx & 127;
    sB[n*ELDA + kw] = packh2(mW1[(64+2*kw)*HID + n], mW1[(64+2*kw+1)*HID + n]);
  }
  __syncthreads();
  mma_fp16_64(acc, aAddr, bAddr, 64);
  __syncthreads();
  #pragma unroll
  for (int mi=0;mi<2;mi++)
    #pragma unroll
    for (int rr=0;rr<2;rr++){
      int r = wm*32 + mi*16 + g + rr*8;
      #pragma unroll
      for (int ni=0;ni<4;ni++){
        int col = wn*32 + ni*8 + 2*t4;
        float v0 = siluf(acc[mi][ni][rr*2+0] + sb1[col]);
        float v1 = siluf(acc[mi][ni][rr*2+1] + sb1[col+1]);
        sA[r*ELDA + (col>>1)] = packh2(v0, v1);
      }
    }
  for (int idx = tid; idx < 64*128; idx += 256){
    int kw = idx >> 7, n = idx & 127;
    sB[n*ELDA + kw] = (n < OUTF)
      ? packh2(mW2[(2*kw)*OUTF + n], mW2[(2*kw+1)*OUTF + n]) : 0u;
  }
  __syncthreads();
  zero_acc2(acc);
  mma_fp16_64(acc, aAddr, bAddr, 64);
  float aSu[8], aSq[8];
  #pragma unroll
  for (int q=0;q<8;q++){ aSu[q]=0.f; aSq[q]=0.f; }
  #pragma unroll
  for (int mi=0;mi<2;mi++)
    #pragma unroll
    for (int rr=0;rr<2;rr++){
      int r = wm*32 + mi*16 + g + rr*8;
      #pragma unroll
      for (int ni=0;ni<4;ni++){
        int col = wn*32 + ni*8 + 2*t4;
        if (col < OUTF){
          float v0 = siluf(acc[mi][ni][rr*2+0] + sb2v[col]);
          float v1 = siluf(acc[mi][ni][rr*2+1] + sb2v[col+1]);
          *(float2*)(g_o + ((size_t)(b*NN + m0 + r))*OUTF + col) = make_float2(v0,v1);
          aSu[ni*2+0]+=v0; aSq[ni*2+0]+=v0*v0;
          aSu[ni*2+1]+=v1; aSq[ni*2+1]+=v1*v1;
        }
      }
    }
  #pragma unroll
  for (int q = 0; q < 8; q++){
    #pragma unroll
    for (int mk = 4; mk <= 16; mk <<= 1){
      aSu[q] += __shfl_xor_sync(0xffffffffu, aSu[q], mk);
      aSq[q] += __shfl_xor_sync(0xffffffffu, aSq[q], mk);
    }
  }
  if (g == 0){
    #pragma unroll
    for (int ni=0;ni<4;ni++){
      int col = wn*32 + ni*8 + 2*t4;
      if (col < OUTF){
        atomicAdd(&sSu[col], aSu[ni*2]);   atomicAdd(&sSu[col+1], aSu[ni*2+1]);
        atomicAdd(&sSq[col], aSq[ni*2]);   atomicAdd(&sSq[col+1], aSq[ni*2+1]);
      }
    }
  }
  __syncthreads();
  if (tid < OUTF){ g_mS[bid*OUTF+tid]=sSu[tid]; g_mQ[bid*OUTF+tid]=sSq[tid]; }
}

__global__ void k_mred(const float* __restrict__ mg, const float* __restrict__ mbt){
  int c = threadIdx.x;
  float s=0.f, q=0.f;
  for (int b=0;b<2*BB;b++){ s+=g_mS[b*OUTF+c]; q+=g_mQ[b*OUTF+c]; }
  float inv = 1.f/((float)BB*NN);
  float m = s*inv, v = q*inv - m*m;
  float ka = mg[c]/sqrtf(v+1e-5f);
  g_mka[c]=ka; g_mkb[c]=mbt[c]-m*ka;
}

__global__ void k_final(const float* __restrict__ nmask, float* __restrict__ out){
  int idx = blockIdx.x*256 + threadIdx.x;
  if (idx >= NODE_OUT) return;
  int c = idx & 63; int row = idx >> 6;
  out[idx] = (g_mka[c]*g_o[idx] + g_mkb[c]) * nmask[row];
}

extern "C" void kernel_launch(void* const* d_in, const int* in_sizes, int n_in,
                              void* d_out, int out_size) {
  const float* x    = (const float*)d_in[0];
  const float* nmsk = (const float*)d_in[1];
  const float* emsk = (const float*)d_in[2];
  const float* eW1  = (const float*)d_in[3];
  const float* eb1  = (const float*)d_in[4];
  const float* eW2  = (const float*)d_in[5];
  const float* eb2  = (const float*)d_in[6];
  const float* eg   = (const float*)d_in[7];
  const float* ebt  = (const float*)d_in[8];
  const float* nW1  = (const float*)d_in[9];
  const float* nb1  = (const float*)d_in[10];
  const float* nW2  = (const float*)d_in[11];
  const float* nb2  = (const float*)d_in[12];
  const float* ng   = (const float*)d_in[13];
  const float* nbt  = (const float*)d_in[14];
  const float* mW1  = (const float*)d_in[15];
  const float* mb1  = (const float*)d_in[16];
  const float* mW2  = (const float*)d_in[17];
  const float* mb2  = (const float*)d_in[18];
  const float* mg   = (const float*)d_in[19];
  const float* mbt  = (const float*)d_in[20];
  float* out = (float*)d_out;
  float* mij = out + NODE_OUT;

  const int PR_SMEM = (128*128 + 8*64) * 4;
  cudaFuncSetAttribute(k_pr,    cudaFuncAttributeMaxDynamicSharedMemorySize, PR_SMEM);
  cudaFuncSetAttribute(k_edge,  cudaFuncAttributeMaxDynamicSharedMemorySize, E2SMEM_BYTES);
  cudaFuncSetAttribute(k_node1, cudaFuncAttributeMaxDynamicSharedMemorySize, NSMEM_BYTES);
  cudaFuncSetAttribute(k_node2, cudaFuncAttributeMaxDynamicSharedMemorySize, NSMEM_BYTES);

  k_pr<<<BB*NN/8, 256, PR_SMEM>>>(x, eW1, eb1);
  k_edge<<<EG2, 256, E2SMEM_BYTES>>>(eW2, eb2);
  k_ecol<<<HID, 256>>>(eg, ebt);
  k_affine<<<BB*NN, 256>>>(emsk, mij);
  k_node1<<<2*BB, 256, NSMEM_BYTES>>>(nW1, nb1, nW2, nb2);
  k_nred<<<1, 128>>>(ng, nbt);
  k_node2<<<2*BB, 256, NSMEM_BYTES>>>(x, nmsk, mW1, mb1, mW2, mb2);
  k_mred<<<1, 64>>>(mg, mbt);
  k_final<<<(NODE_OUT+255)/256, 256>>>(nmsk, out);
}

// round 17
// speedup vs baseline: 1.0306x; 1.0306x over previous
#include <cuda_runtime.h>
#include <cuda_fp16.h>
#include <cstdint>

#define BB 32
#define NN 128
#define IN_F 64
#define HID 128
#define OUTF 64
#define EE (NN*(NN-1))
#define DEG (NN-1)
#define NODE_OUT (BB*NN*OUTF)

// fp16-packed layout: u32 words, stride 68
#define ELDA 68
#define EB_OFF (128*ELDA)
#define EF_OFF (2*128*ELDA)
#define ESMEM_U32 (2*128*ELDA + 1024)
#define ESMEM_BYTES (ESMEM_U32*4)
#define EDGE_GRID 304

// node-kernel layout: sA 64 rows, sB 128 rows
#define NA_ROWS 64
#define NB_OFF (NA_ROWS*ELDA)
#define NF_OFF (NB_OFF + 128*ELDA)
#define NSMEM_BYTES ((NF_OFF + 768)*4)

// ---- scratch (device globals, allocation-free) ----
__device__ float g_P[BB*NN*HID];
__device__ float g_R[BB*NN*HID];
__device__ float g_pSu[EDGE_GRID*HID];
__device__ float g_pQu[EDGE_GRID*HID];
__device__ float g_inc[BB*NN*HID];
__device__ float g_eka[HID];
__device__ float g_ekb[HID];
__device__ float g_hn2[BB*NN*HID];
__device__ float g_nS[2*BB*HID];
__device__ float g_nQ[2*BB*HID];
__device__ float g_nka[HID];
__device__ float g_nkb[HID];
__device__ float g_o[BB*NN*OUTF];
__device__ float g_mS[2*BB*OUTF];
__device__ float g_mQ[2*BB*OUTF];
__device__ float g_mka[OUTF];
__device__ float g_mkb[OUTF];
__device__ uint32_t g_h2[BB*EE*HID/2];

__device__ __forceinline__ float siluf(float x){
  float h = 0.5f * x;
  float t;
  asm("tanh.approx.f32 %0, %1;" : "=f"(t) : "f"(h));
  return fmaf(h, t, h);
}
__device__ __forceinline__ uint32_t packh2(float a, float b){
  __half2 h = __floats2half2_rn(a, b);
  return *(uint32_t*)&h;
}
__device__ __forceinline__ uint32_t smem_addr_u32(const void* p){
  return (uint32_t)__cvta_generic_to_shared(p);
}
__device__ __forceinline__ void zero_acc4(float (&acc)[4][4][4]){
  #pragma unroll
  for (int i=0;i<4;i++)
    #pragma unroll
    for (int j=0;j<4;j++)
      #pragma unroll
      for (int k=0;k<4;k++) acc[i][j][k]=0.f;
}
__device__ __forceinline__ void zero_acc2(float (&acc)[2][4][4]){
  #pragma unroll
  for (int i=0;i<2;i++)
    #pragma unroll
    for (int j=0;j<4;j++)
      #pragma unroll
      for (int k=0;k<4;k++) acc[i][j][k]=0.f;
}

// fp16 ldmatrix+mma: 128x128 tile, 8 warps (2m x 4n, 64x32)
__device__ __forceinline__ void mma_fp16(float (&acc)[4][4][4],
                                         const uint32_t aA[4], const uint32_t bA[4],
                                         int Kw)
{
  for (int kw0 = 0; kw0 < Kw; kw0 += 8){
    uint32_t a[4][4];
    #pragma unroll
    for (int mi = 0; mi < 4; mi++)
      asm volatile(
        "ldmatrix.sync.aligned.m8n8.x4.shared.b16 {%0,%1,%2,%3}, [%4];"
        : "=r"(a[mi][0]), "=r"(a[mi][1]), "=r"(a[mi][2]), "=r"(a[mi][3])
        : "r"(aA[mi] + kw0*4));
    uint32_t bf[4][2];
    #pragma unroll
    for (int ni = 0; ni < 4; ni++)
      asm volatile(
        "ldmatrix.sync.aligned.m8n8.x2.shared.b16 {%0,%1}, [%2];"
        : "=r"(bf[ni][0]), "=r"(bf[ni][1])
        : "r"(bA[ni] + kw0*4));
    #pragma unroll
    for (int mi = 0; mi < 4; mi++)
      #pragma unroll
      for (int ni = 0; ni < 4; ni++)
        asm volatile(
          "mma.sync.aligned.m16n8k16.row.col.f32.f16.f16.f32 "
          "{%0,%1,%2,%3},{%4,%5,%6,%7},{%8,%9},{%0,%1,%2,%3};\n"
          : "+f"(acc[mi][ni][0]), "+f"(acc[mi][ni][1]),
            "+f"(acc[mi][ni][2]), "+f"(acc[mi][ni][3])
          : "r"(a[mi][0]), "r"(a[mi][1]), "r"(a[mi][2]), "r"(a[mi][3]),
            "r"(bf[ni][0]), "r"(bf[ni][1]));
  }
}

// fp16 ldmatrix+mma: 64x128 tile, 8 warps (2m x 4n, 32x32)
__device__ __forceinline__ void mma_fp16_64(float (&acc)[2][4][4],
                                            const uint32_t aA[2], const uint32_t bA[4],
                                            int Kw)
{
  for (int kw0 = 0; kw0 < Kw; kw0 += 8){
    uint32_t a[2][4];
    #pragma unroll
    for (int mi = 0; mi < 2; mi++)
      asm volatile(
        "ldmatrix.sync.aligned.m8n8.x4.shared.b16 {%0,%1,%2,%3}, [%4];"
        : "=r"(a[mi][0]), "=r"(a[mi][1]), "=r"(a[mi][2]), "=r"(a[mi][3])
        : "r"(aA[mi] + kw0*4));
    uint32_t bf[4][2];
    #pragma unroll
    for (int ni = 0; ni < 4; ni++)
      asm volatile(
        "ldmatrix.sync.aligned.m8n8.x2.shared.b16 {%0,%1}, [%2];"
        : "=r"(bf[ni][0]), "=r"(bf[ni][1])
        : "r"(bA[ni] + kw0*4));
    #pragma unroll
    for (int mi = 0; mi < 2; mi++)
      #pragma unroll
      for (int ni = 0; ni < 4; ni++)
        asm volatile(
          "mma.sync.aligned.m16n8k16.row.col.f32.f16.f16.f32 "
          "{%0,%1,%2,%3},{%4,%5,%6,%7},{%8,%9},{%0,%1,%2,%3};\n"
          : "+f"(acc[mi][ni][0]), "+f"(acc[mi][ni][1]),
            "+f"(acc[mi][ni][2]), "+f"(acc[mi][ni][3])
          : "r"(a[mi][0]), "r"(a[mi][1]), "r"(a[mi][2]), "r"(a[mi][3]),
            "r"(bf[ni][0]), "r"(bf[ni][1]));
  }
}

// ---- P/R precompute ----
__global__ void k_pr(const float* __restrict__ x, const float* __restrict__ eW1,
                     const float* __restrict__ eb1)
{
  extern __shared__ float sw[];
  float* sx = sw + 128*128;
  int tid = threadIdx.x;
  int n0 = blockIdx.x * 8;
  for (int idx = tid; idx < 128*128; idx += 256) sw[idx] = eW1[idx];
  for (int idx = tid; idx < 8*64; idx += 256)
    sx[idx] = x[(size_t)n0*IN_F + idx];
  __syncthreads();
  int c = tid & 127;
  for (int it = 0; it < 4; it++){
    int nl = it*2 + (tid >> 7);
    const float* xr = sx + nl*64;
    float p = 0.f, r = 0.f;
    #pragma unroll 8
    for (int k = 0; k < 64; k++){
      float xv = xr[k];
      p += xv * sw[k*128 + c];
      r += xv * sw[(64+k)*128 + c];
    }
    size_t o = (size_t)(n0 + nl)*HID + c;
    g_P[o] = p;
    g_R[o] = r + eb1[c];
  }
}

// ---- persistent edge kernel: M-128, 2 CTAs/SM, R via __ldg ----
__global__ void __launch_bounds__(256,2)
k_edge(const float* __restrict__ eW2, const float* __restrict__ eb2)
{
  extern __shared__ uint32_t sm[];
  uint32_t* sA = sm;
  uint32_t* sB = sm + EB_OFF;
  float* sF  = (float*)(sm + EF_OFF);
  float* sb2 = sF;
  float* sPSu= sF+256;   float* sPQu= sF+512;

  int tid = threadIdx.x, lane = tid & 31, wid = tid >> 5;
  int wm = wid >> 2, wn = wid & 3;
  int g = lane >> 2, t4 = lane & 3;

  for (int idx = tid; idx < 64*128; idx += 256){
    int kw = idx >> 7, n = idx & 127;
    sB[n*ELDA + kw] = packh2(eW2[(2*kw)*HID + n], eW2[(2*kw+1)*HID + n]);
  }
  if (tid < 128) sb2[tid] = eb2[tid];
  __syncthreads();

  uint32_t aAddr[4], bAddr[4];
  {
    int arow = wm*64 + (lane & 15);
    int akw  = (lane >> 4) * 4;
    #pragma unroll
    for (int mi = 0; mi < 4; mi++)
      aAddr[mi] = smem_addr_u32(sA + (arow + mi*16)*ELDA + akw);
    int brow = wn*32 + (lane & 7);
    int bkw  = ((lane >> 3) & 1) * 4;
    #pragma unroll
    for (int ni = 0; ni < 4; ni++)
      bAddr[ni] = smem_addr_u32(sB + (brow + ni*8)*ELDA + bkw);
  }

  float aSu[8], aSq[8];
  #pragma unroll
  for (int q=0;q<8;q++){ aSu[q]=0.f; aSq[q]=0.f; }

  for (int grp = blockIdx.x; grp < BB*NN; grp += EDGE_GRID){
    int b = grp >> 7, i = grp & 127;

    { // A rows: silu(P[j]+R[i]); R via L1-broadcast __ldg (no staging sync)
      int r = tid >> 1, h = tid & 1;
      uint2* Ar2 = (uint2*)(sA + r*ELDA + h*32);
      if (r < DEG){
        int j = (r < i) ? r : r + 1;
        const float* Pr = g_P + ((size_t)(b*NN + j))*HID + h*64;
        const float* Rr = g_R + (size_t)grp*HID + h*64;
        #pragma unroll
        for (int c = 0; c < 64; c += 4){
          float4 p  = *(const float4*)(Pr + c);
          float4 rv = __ldg((const float4*)(Rr + c));
          float x0 = siluf(p.x + rv.x);
          float x1 = siluf(p.y + rv.y);
          float x2 = siluf(p.z + rv.z);
          float x3 = siluf(p.w + rv.w);
          Ar2[c/4] = make_uint2(packh2(x0, x1), packh2(x2, x3));
        }
      } else {
        #pragma unroll
        for (int w = 0; w < 16; w++) Ar2[w] = make_uint2(0u, 0u);
      }
    }
    __syncthreads();

    float acc[4][4][4]; zero_acc4(acc);
    mma_fp16(acc, aAddr, bAddr, 64);

    size_t obase2 = ((size_t)grp*DEG*HID) >> 1;
    #pragma unroll
    for (int mi = 0; mi < 4; mi++)
      #pragma unroll
      for (int rr = 0; rr < 2; rr++){
        int r = wm*64 + mi*16 + g + rr*8;
        if (r < DEG){
          #pragma unroll
          for (int ni = 0; ni < 4; ni++){
            int col = wn*32 + ni*8 + 2*t4;
            float v0 = siluf(acc[mi][ni][rr*2+0] + sb2[col]);
            float v1 = siluf(acc[mi][ni][rr*2+1] + sb2[col+1]);
            g_h2[obase2 + (((size_t)r*HID + col) >> 1)] = packh2(v0, v1);
            aSu[ni*2+0]+=v0; aSq[ni*2+0]+=v0*v0;
            aSu[ni*2+1]+=v1; aSq[ni*2+1]+=v1*v1;
          }
        }
      }
    __syncthreads();
  }

  #pragma unroll
  for (int q = 0; q < 8; q++){
    #pragma unroll
    for (int mk = 4; mk <= 16; mk <<= 1){
      aSu[q] += __shfl_xor_sync(0xffffffffu, aSu[q], mk);
      aSq[q] += __shfl_xor_sync(0xffffffffu, aSq[q], mk);
    }
  }
  if (g == 0){
    #pragma unroll
    for (int ni = 0; ni < 4; ni++){
      int col = wn*32 + ni*8 + 2*t4;
      sPSu[wm*128+col]   = aSu[ni*2];   sPSu[wm*128+col+1] = aSu[ni*2+1];
      sPQu[wm*128+col]   = aSq[ni*2];   sPQu[wm*128+col+1] = aSq[ni*2+1];
    }
  }
  __syncthreads();
  if (tid < 128){
    g_pSu[(size_t)blockIdx.x*HID + tid] = sPSu[tid] + sPSu[128+tid];
    g_pQu[(size_t)blockIdx.x*HID + tid] = sPQu[tid] + sPQu[128+tid];
  }
}

// ---- edge BN coefficients ----
__global__ void k_ecol(const float* __restrict__ eg, const float* __restrict__ ebt){
  __shared__ float rS[256], rQ[256];
  int c = blockIdx.x, t = threadIdx.x;
  float s=0.f, q=0.f;
  for (int r=t; r<EDGE_GRID; r+=256){ s += g_pSu[r*HID+c]; q += g_pQu[r*HID+c]; }
  rS[t]=s; rQ[t]=q; __syncthreads();
  for (int o=128;o>0;o>>=1){ if(t<o){rS[t]+=rS[t+o];rQ[t]+=rQ[t+o];} __syncthreads(); }
  if (t==0){
    float inv = 1.f/((float)BB*(float)EE);
    float m = rS[0]*inv, v = rQ[0]*inv - m*m;
    float ka = eg[c]/sqrtf(v+1e-5f);
    g_eka[c]=ka; g_ekb[c]=ebt[c]-m*ka;
  }
}

// ---- BN affine * em^2 per group (grid=4096) ----
__global__ void k_affine(const float* __restrict__ em, float* __restrict__ mij){
  __shared__ float ka[HID], kb[HID], sEm[HID];
  __shared__ float sP[8*HID];
  int grp = blockIdx.x; int b = grp >> 7; int i = grp & 127;
  int t = threadIdx.x;
  if (t < 128){ ka[t]=g_eka[t]; kb[t]=g_ekb[t]; }
  else {
    int r = t - 128;
    float e = (r < DEG) ? em[(size_t)b*EE + (size_t)i*DEG + r] : 0.f;
    sEm[r] = e*e;
  }
  __syncthreads();
  int wp = t & 31;
  int rh = t >> 5;
  int c4 = wp*4;
  float k0=ka[c4],  k1=ka[c4+1], k2=ka[c4+2], k3=ka[c4+3];
  float d0=kb[c4],  d1=kb[c4+1], d2=kb[c4+2], d3=kb[c4+3];
  float s0=0.f, s1=0.f, s2=0.f, s3=0.f;
  size_t gbase = ((size_t)grp*DEG*HID) >> 1;
  for (int r = rh; r < DEG; r += 8){
    uint2 p = *(const uint2*)(g_h2 + gbase + (size_t)r*64 + wp*2);
    float2 h0 = __half22float2(*(__half2*)&p.x);
    float2 h1 = __half22float2(*(__half2*)&p.y);
    float wgt = sEm[r];
    float v0 = (k0*h0.x + d0)*wgt;
    float v1 = (k1*h0.y + d1)*wgt;
    float v2 = (k2*h1.x + d2)*wgt;
    float v3 = (k3*h1.y + d3)*wgt;
    *(float4*)(mij + ((size_t)grp*DEG + r)*HID + c4) = make_float4(v0,v1,v2,v3);
    s0+=v0; s1+=v1; s2+=v2; s3+=v3;
  }
  float* row = sP + rh*HID + c4;
  row[0]=s0; row[1]=s1; row[2]=s2; row[3]=s3;
  __syncthreads();
  if (t < 128){
    float s = 0.f;
    #pragma unroll
    for (int q = 0; q < 8; q++) s += sP[q*HID + t];
    g_inc[(size_t)grp*HID + t] = s * (1.f/(float)NN);
  }
}

// ---- node MLP 1: grid 64, M-tile 64 ----
__global__ void __launch_bounds__(256,2)
k_node1(const float* __restrict__ nW1, const float* __restrict__ nb1,
        const float* __restrict__ nW2, const float* __restrict__ nb2)
{
  extern __shared__ uint32_t sm[];
  uint32_t* sA = sm; uint32_t* sB = sm + NB_OFF;
  float* sF = (float*)(sm + NF_OFF);
  float* sb1 = sF;     float* sb2v = sF+128;
  float* sSu = sF+256; float* sSq = sF+384;
  int bid = blockIdx.x; int b = bid >> 1; int m0 = (bid & 1)*64;
  int tid = threadIdx.x; int lane = tid & 31; int wid = tid >> 5;
  int wm = wid >> 2, wn = wid & 3, g = lane >> 2, t4 = lane & 3;

  uint32_t aAddr[2], bAddr[4];
  {
    int arow = wm*32 + (lane & 15);
    int akw  = (lane >> 4) * 4;
    #pragma unroll
    for (int mi = 0; mi < 2; mi++)
      aAddr[mi] = smem_addr_u32(sA + (arow + mi*16)*ELDA + akw);
    int brow = wn*32 + (lane & 7);
    int bkw  = ((lane >> 3) & 1) * 4;
    #pragma unroll
    for (int ni = 0; ni < 4; ni++)
      bAddr[ni] = smem_addr_u32(sB + (brow + ni*8)*ELDA + bkw);
  }

  if (tid < 128){
    sb1[tid]=nb1[tid];   sb2v[tid]=nb2[tid];
    sSu[tid]=0.f; sSq[tid]=0.f;
  }
  {
    int r = tid >> 2, h = tid & 3;
    const float* ir = g_inc + ((size_t)(b*NN + m0 + r))*HID + h*32;
    uint2* Ar2 = (uint2*)(sA + r*ELDA + h*16);
    #pragma unroll
    for (int c = 0; c < 32; c += 4){
      float4 v = *(const float4*)(ir + c);
      Ar2[c/4] = make_uint2(packh2(v.x, v.y), packh2(v.z, v.w));
    }
  }
  for (int idx = tid; idx < 64*128; idx += 256){
    int kw = idx >> 7, n = idx & 127;
    sB[n*ELDA + kw] = packh2(nW1[(2*kw)*HID + n], nW1[(2*kw+1)*HID + n]);
  }
  __syncthreads();
  float acc[2][4][4]; zero_acc2(acc);
  mma_fp16_64(acc, aAddr, bAddr, 64);
  __syncthreads();
  #pragma unroll
  for (int mi=0;mi<2;mi++)
    #pragma unroll
    for (int rr=0;rr<2;rr++){
      int r = wm*32 + mi*16 + g + rr*8;
      #pragma unroll
      for (int ni=0;ni<4;ni++){
        int col = wn*32 + ni*8 + 2*t4;
        float v0 = siluf(acc[mi][ni][rr*2+0] + sb1[col]);
        float v1 = siluf(acc[mi][ni][rr*2+1] + sb1[col+1]);
        sA[r*ELDA + (col>>1)] = packh2(v0, v1);
      }
    }
  for (int idx = tid; idx < 64*128; idx += 256){
    int kw = idx >> 7, n = idx & 127;
    sB[n*ELDA + kw] = packh2(nW2[(2*kw)*HID + n], nW2[(2*kw+1)*HID + n]);
  }
  __syncthreads();
  zero_acc2(acc);
  mma_fp16_64(acc, aAddr, bAddr, 64);
  float aSu[8], aSq[8];
  #pragma unroll
  for (int q=0;q<8;q++){ aSu[q]=0.f; aSq[q]=0.f; }
  #pragma unroll
  for (int mi=0;mi<2;mi++)
    #pragma unroll
    for (int rr=0;rr<2;rr++){
      int r = wm*32 + mi*16 + g + rr*8;
      #pragma unroll
      for (int ni=0;ni<4;ni++){
        int col = wn*32 + ni*8 + 2*t4;
        float v0 = siluf(acc[mi][ni][rr*2+0] + sb2v[col]);
        float v1 = siluf(acc[mi][ni][rr*2+1] + sb2v[col+1]);
        *(float2*)(g_hn2 + ((size_t)(b*NN + m0 + r))*HID + col) = make_float2(v0,v1);
        aSu[ni*2+0]+=v0; aSq[ni*2+0]+=v0*v0;
        aSu[ni*2+1]+=v1; aSq[ni*2+1]+=v1*v1;
      }
    }
  #pragma unroll
  for (int q = 0; q < 8; q++){
    #pragma unroll
    for (int mk = 4; mk <= 16; mk <<= 1){
      aSu[q] += __shfl_xor_sync(0xffffffffu, aSu[q], mk);
      aSq[q] += __shfl_xor_sync(0xffffffffu, aSq[q], mk);
    }
  }
  if (g == 0){
    #pragma unroll
    for (int ni=0;ni<4;ni++){
      int col = wn*32 + ni*8 + 2*t4;
      atomicAdd(&sSu[col], aSu[ni*2]);   atomicAdd(&sSu[col+1], aSu[ni*2+1]);
      atomicAdd(&sSq[col], aSq[ni*2]);   atomicAdd(&sSq[col+1], aSq[ni*2+1]);
    }
  }
  __syncthreads();
  if (tid < 128){ g_nS[bid*HID+tid]=sSu[tid]; g_nQ[bid*HID+tid]=sSq[tid]; }
}

__global__ void k_nred(const float* __restrict__ ng, const float* __restrict__ nbt){
  int c = threadIdx.x;
  float s=0.f, q=0.f;
  for (int b=0;b<2*BB;b++){ s+=g_nS[b*HID+c]; q+=g_nQ[b*HID+c]; }
  float inv = 1.f/((float)BB*NN);
  float m = s*inv, v = q*inv - m*m;
  float ka = ng[c]/sqrtf(v+1e-5f);
  g_nka[c]=ka; g_nkb[c]=nbt[c]-m*ka;
}

// ---- node MLP 2: grid 64, M-tile 64 ----
__global__ void __launch_bounds__(256,2)
k_node2(const float* __restrict__ x, const float* __restrict__ nmask,
        const float* __restrict__ mW1, const float* __restrict__ mb1,
        const float* __restrict__ mW2, const float* __restrict__ mb2)
{
  extern __shared__ uint32_t sm[];
  uint32_t* sA = sm; uint32_t* sB = sm + NB_OFF;
  float* sF = (float*)(sm + NF_OFF);
  float* ska = sF;     float* skb = sF+128;
  float* sb1 = sF+256; float* sb2v = sF+384;
  float* sSu = sF+512; float* sSq = sF+640;
  int bid = blockIdx.x; int b = bid >> 1; int m0 = (bid & 1)*64;
  int tid = threadIdx.x; int lane = tid & 31; int wid = tid >> 5;
  int wm = wid >> 2, wn = wid & 3, g = lane >> 2, t4 = lane & 3;

  uint32_t aAddr[2], bAddr[4];
  {
    int arow = wm*32 + (lane & 15);
    int akw  = (lane >> 4) * 4;
    #pragma unroll
    for (int mi = 0; mi < 2; mi++)
      aAddr[mi] = smem_addr_u32(sA + (arow + mi*16)*ELDA + akw);
    int brow = wn*32 + (lane & 7);
    int bkw  = ((lane >> 3) & 1) * 4;
    #pragma unroll
    for (int ni = 0; ni < 4; ni++)
      bAddr[ni] = smem_addr_u32(sB + (brow + ni*8)*ELDA + bkw);
  }

  if (tid < 128){
    ska[tid]=g_nka[tid]; skb[tid]=g_nkb[tid];
    sb1[tid]=mb1[tid];
    sSu[tid]=0.f; sSq[tid]=0.f;
  }
  if (tid < 64) sb2v[tid]=mb2[tid];
  {
    int r = tid >> 2, h = tid & 3;
    const float* xr = x + ((size_t)(b*NN + m0 + r))*IN_F + h*16;
    uint2* Ar2 = (uint2*)(sA + r*ELDA + h*8);
    #pragma unroll
    for (int c = 0; c < 16; c += 4){
      float4 v = *(const float4*)(xr + c);
      Ar2[c/4] = make_uint2(packh2(v.x, v.y), packh2(v.z, v.w));
    }
  }
  for (int idx = tid; idx < 32*128; idx += 256){
    int kw = idx >> 7, n = idx & 127;
    sB[n*ELDA + kw] = packh2(mW1[(2*kw)*HID + n], mW1[(2*kw+1)*HID + n]);
  }
  __syncthreads();
  float acc[2][4][4]; zero_acc2(acc);
  mma_fp16_64(acc, aAddr, bAddr, 32);
  __syncthreads();
  {
    int r = tid >> 2, h = tid & 3;
    int gr = b*NN + m0 + r;
    float msk = nmask[gr];
    const float* hr = g_hn2 + (size_t)gr*HID + h*32;
    const float* kap = ska + h*32; const float* kbp = skb + h*32;
    uint2* Ar2 = (uint2*)(sA + r*ELDA + h*16);
    #pragma unroll
    for (int c = 0; c < 32; c += 4){
      float v0 = (kap[c]*hr[c] + kbp[c]) * msk;
      float v1 = (kap[c+1]*hr[c+1] + kbp[c+1]) * msk;
      float v2 = (kap[c+2]*hr[c+2] + kbp[c+2]) * msk;
      float v3 = (kap[c+3]*hr[c+3] + kbp[c+3]) * msk;
      Ar2[c/4] = make_uint2(packh2(v0, v1), packh2(v2, v3));
    }
  }
  for (int idx = tid; idx < 64*128; idx += 256){
    int kw = idx >> 7, n = idx & 127;
    sB[n*ELDA + kw] = packh2(mW1[(64+2*kw)*HID + n], mW1[(64+2*kw+1)*HID + n]);
  }
  __syncthreads();
  mma_fp16_64(acc, aAddr, bAddr, 64);
  __syncthreads();
  #pragma unroll
  for (int mi=0;mi<2;mi++)
    #pragma unroll
    for (int rr=0;rr<2;rr++){
      int r = wm*32 + mi*16 + g + rr*8;
      #pragma unroll
      for (int ni=0;ni<4;ni++){
        int col = wn*32 + ni*8 + 2*t4;
        float v0 = siluf(acc[mi][ni][rr*2+0] + sb1[col]);
        float v1 = siluf(acc[mi][ni][rr*2+1] + sb1[col+1]);
        sA[r*ELDA + (col>>1)] = packh2(v0, v1);
      }
    }
  for (int idx = tid; idx < 64*128; idx += 256){
    int kw = idx >> 7, n = idx & 127;
    sB[n*ELDA + kw] = (n < OUTF)
      ? packh2(mW2[(2*kw)*OUTF + n], mW2[(2*kw+1)*OUTF + n]) : 0u;
  }
  __syncthreads();
  zero_acc2(acc);
  mma_fp16_64(acc, aAddr, bAddr, 64);
  float aSu[8], aSq[8];
  #pragma unroll
  for (int q=0;q<8;q++){ aSu[q]=0.f; aSq[q]=0.f; }
  #pragma unroll
  for (int mi=0;mi<2;mi++)
    #pragma unroll
    for (int rr=0;rr<2;rr++){
      int r = wm*32 + mi*16 + g + rr*8;
      #pragma unroll
      for (int ni=0;ni<4;ni++){
        int col = wn*32 + ni*8 + 2*t4;
        if (col < OUTF){
          float v0 = siluf(acc[mi][ni][rr*2+0] + sb2v[col]);
          float v1 = siluf(acc[mi][ni][rr*2+1] + sb2v[col+1]);
          *(float2*)(g_o + ((size_t)(b*NN + m0 + r))*OUTF + col) = make_float2(v0,v1);
          aSu[ni*2+0]+=v0; aSq[ni*2+0]+=v0*v0;
          aSu[ni*2+1]+=v1; aSq[ni*2+1]+=v1*v1;
        }
      }
    }
  #pragma unroll
  for (int q = 0; q < 8; q++){
    #pragma unroll
    for (int mk = 4; mk <= 16; mk <<= 1){
      aSu[q] += __shfl_xor_sync(0xffffffffu, aSu[q], mk);
      aSq[q] += __shfl_xor_sync(0xffffffffu, aSq[q], mk);
    }
  }
  if (g == 0){
    #pragma unroll
    for (int ni=0;ni<4;ni++){
      int col = wn*32 + ni*8 + 2*t4;
      if (col < OUTF){
        atomicAdd(&sSu[col], aSu[ni*2]);   atomicAdd(&sSu[col+1], aSu[ni*2+1]);
        atomicAdd(&sSq[col], aSq[ni*2]);   atomicAdd(&sSq[col+1], aSq[ni*2+1]);
      }
    }
  }
  __syncthreads();
  if (tid < OUTF){ g_mS[bid*OUTF+tid]=sSu[tid]; g_mQ[bid*OUTF+tid]=sSq[tid]; }
}

__global__ void k_mred(const float* __restrict__ mg, const float* __restrict__ mbt){
  int c = threadIdx.x;
  float s=0.f, q=0.f;
  for (int b=0;b<2*BB;b++){ s+=g_mS[b*OUTF+c]; q+=g_mQ[b*OUTF+c]; }
  float inv = 1.f/((float)BB*NN);
  float m = s*inv, v = q*inv - m*m;
  float ka = mg[c]/sqrtf(v+1e-5f);
  g_mka[c]=ka; g_mkb[c]=mbt[c]-m*ka;
}

__global__ void k_final(const float* __restrict__ nmask, float* __restrict__ out){
  int idx = blockIdx.x*256 + threadIdx.x;
  if (idx >= NODE_OUT) return;
  int c = idx & 63; int row = idx >> 6;
  out[idx] = (g_mka[c]*g_o[idx] + g_mkb[c]) * nmask[row];
}

extern "C" void kernel_launch(void* const* d_in, const int* in_sizes, int n_in,
                              void* d_out, int out_size) {
  const float* x    = (const float*)d_in[0];
  const float* nmsk = (const float*)d_in[1];
  const float* emsk = (const float*)d_in[2];
  const float* eW1  = (const float*)d_in[3];
  const float* eb1  = (const float*)d_in[4];
  const float* eW2  = (const float*)d_in[5];
  const float* eb2  = (const float*)d_in[6];
  const float* eg   = (const float*)d_in[7];
  const float* ebt  = (const float*)d_in[8];
  const float* nW1  = (const float*)d_in[9];
  const float* nb1  = (const float*)d_in[10];
  const float* nW2  = (const float*)d_in[11];
  const float* nb2  = (const float*)d_in[12];
  const float* ng   = (const float*)d_in[13];
  const float* nbt  = (const float*)d_in[14];
  const float* mW1  = (const float*)d_in[15];
  const float* mb1  = (const float*)d_in[16];
  const float* mW2  = (const float*)d_in[17];
  const float* mb2  = (const float*)d_in[18];
  const float* mg   = (const float*)d_in[19];
  const float* mbt  = (const float*)d_in[20];
  float* out = (float*)d_out;
  float* mij = out + NODE_OUT;

  const int PR_SMEM = (128*128 + 8*64) * 4;
  cudaFuncSetAttribute(k_pr,    cudaFuncAttributeMaxDynamicSharedMemorySize, PR_SMEM);
  cudaFuncSetAttribute(k_edge,  cudaFuncAttributeMaxDynamicSharedMemorySize, ESMEM_BYTES);
  cudaFuncSetAttribute(k_node1, cudaFuncAttributeMaxDynamicSharedMemorySize, NSMEM_BYTES);
  cudaFuncSetAttribute(k_node2, cudaFuncAttributeMaxDynamicSharedMemorySize, NSMEM_BYTES);

  k_pr<<<BB*NN/8, 256, PR_SMEM>>>(x, eW1, eb1);
  k_edge<<<EDGE_GRID, 256, ESMEM_BYTES>>>(eW2, eb2);
  k_ecol<<<HID, 256>>>(eg, ebt);
  k_affine<<<BB*NN, 256>>>(emsk, mij);
  k_node1<<<2*BB, 256, NSMEM_BYTES>>>(nW1, nb1, nW2, nb2);
  k_nred<<<1, 128>>>(ng, nbt);
  k_node2<<<2*BB, 256, NSMEM_BYTES>>>(x, nmsk, mW1, mb1, mW2, mb2);
  k_mred<<<1, 64>>>(mg, mbt);
  k_final<<<(NODE_OUT+255)/256, 256>>>(nmsk, out);
}